// round 9
// baseline (speedup 1.0000x reference)
#include <cuda_runtime.h>
#include <cstdint>

// KAN layer as GEMM: out[1024,128] = A[1024,1024] @ B[1024,128] + bias
//   A[n, j*8+k] = Catmull-Rom basis weight (built per n-tile in SMEM, value-duplicated pairs)
//   B[k, o]     = weights[o,j]*coeffs[o,j,k&7]  (row-major [k][o], built once, 512 KB)
//
// Main kernel: grid = 128 n-tiles x 2 o-halves = 256 blocks, 256 threads (8 warps).
//   warp = K-eighth (128 k); khalf = lane>>4 -> 64-k sub-slice; pg = lane&15 -> 2 o-pairs.
//   Thread tile: 8 rows x 4 o x 64 k, o-packed f32x2 accumulators (acc[8][2]).
//   Reduce: shfl_xor(16) khalf fold -> SMEM (aliased on A tile) across 8 warps.

#define D_IN  128
#define D_OUT 128
#define KNOTS 8
#define N_ROWS 1024
#define JK (D_IN * KNOTS)          // 1024 = K of the GEMM
#define ROWS 8
#define SMEM_BYTES (ROWS * JK * 8) // 64 KB dynamic

typedef unsigned long long u64;

__device__ float g_WC2[JK * D_OUT];   // [k][o] row-major

__global__ void build_wc_kernel(const float* __restrict__ coeffs,
                                const float* __restrict__ weights) {
    int f = blockIdx.x * blockDim.x + threadIdx.x;   // 0 .. 131071
    int o  = f & (D_OUT - 1);
    int k  = f >> 7;
    int j  = k >> 3;
    int kk = k & 7;
    g_WC2[f] = weights[o * D_IN + j] * coeffs[(o * D_IN + j) * KNOTS + kk];
}

#define FMA2(d, a, b, c) \
    asm("fma.rn.f32x2 %0, %1, %2, %3;" : "=l"(d) : "l"(a), "l"(b), "l"(c))
#define ADD2(d, a, b) \
    asm("add.rn.f32x2 %0, %1, %2;" : "=l"(d) : "l"(a), "l"(b))

__global__ __launch_bounds__(256, 3) void kan_main_kernel(
    const float* __restrict__ x,
    const float* __restrict__ bias,
    float* __restrict__ out) {
    // A tile, value-duplicated: a2[r][k] = {A[r][k], A[r][k]} as u64. 64 KB dynamic.
    // After the mainloop it is re-used as the cross-warp reduction buffer.
    extern __shared__ u64 a2_s[];

    const int tid   = threadIdx.x;
    const int lane  = tid & 31;
    const int kq    = tid >> 5;          // warp = K-eighth
    const int pg    = lane & 15;         // 2 o-pairs: pairs pg*2, pg*2+1 within the half
    const int khalf = lane >> 4;         // which 64-k half of the warp's 128-k slice
    const int n0    = blockIdx.x * ROWS;
    const int ohalf = blockIdx.y;        // 0 or 1

    // ---- Stage 1: build basis tile (8 rows x 128 j), 4 evals/thread ----
    #pragma unroll
    for (int e = tid; e < ROWS * D_IN; e += 256) {
        int nn = e >> 7;
        int j  = e & (D_IN - 1);
        float xv = x[(n0 + nn) * D_IN + j];
        float xc = fminf(fmaxf(xv, -1.0f), 1.0f);
        float t  = (xc + 1.0f) * 3.5f;               // h = 2/7
        int idx  = min((int)floorf(t), 6);
        float u  = t - (float)idx;
        float u2 = u * u, u3 = u2 * u;
        float b0 = 0.5f * (-u3 + 2.0f * u2 - u);
        float b1 = 0.5f * (3.0f * u3 - 5.0f * u2 + 2.0f);
        float b2 = 0.5f * (-3.0f * u3 + 4.0f * u2 + u);
        float b3 = 0.5f * (u3 - u2);
        int p0 = max(idx - 1, 0);
        int p3 = min(idx + 2, 7);
        float v[8];
        #pragma unroll
        for (int k = 0; k < 8; k++) {
            float s = 0.0f;
            s += (k == p0)      ? b0 : 0.0f;
            s += (k == idx)     ? b1 : 0.0f;
            s += (k == idx + 1) ? b2 : 0.0f;
            s += (k == p3)      ? b3 : 0.0f;
            v[k] = s;
        }
        float4* dst = (float4*)&a2_s[nn * JK + j * 8];   // 8 u64 = 4 float4 (dup pairs)
        dst[0] = make_float4(v[0], v[0], v[1], v[1]);
        dst[1] = make_float4(v[2], v[2], v[3], v[3]);
        dst[2] = make_float4(v[4], v[4], v[5], v[5]);
        dst[3] = make_float4(v[6], v[6], v[7], v[7]);
    }
    __syncthreads();

    // ---- Stage 2: mainloop. 32 iterations of 2 k each ----
    const ulonglong2* __restrict__ Bp = (const ulonglong2*)g_WC2;  // 4 floats = 2 o-pairs
    const ulonglong2* __restrict__ Ap = (const ulonglong2*)a2_s;   // {a,a},{a',a'}

    const int k0base = kq * 128 + khalf * 64;        // this lane's first k
    const int abase  = (k0base >> 1);                // ulonglong2 index within a row (512/row)
    // B row = 128 floats = 32 ulonglong2; this thread's 4 floats at o = ohalf*64 + pg*4.
    int bi = k0base * 32 + ohalf * 16 + pg;
    const int bi0 = bi;

    u64 acc[ROWS][2];
    #pragma unroll
    for (int r = 0; r < ROWS; r++) { acc[r][0] = 0ull; acc[r][1] = 0ull; }

    // Prefetch 2 iterations (4 k) ahead to cover L2 latency.
    ulonglong2 c0  = Bp[bi];            ulonglong2 c1  = Bp[bi + 32];
    ulonglong2 d0  = Bp[bi + 64];       ulonglong2 d1  = Bp[bi + 96];

    #pragma unroll 4
    for (int t2 = 0; t2 < 32; t2++) {
        bi += 64;
        int bn = (t2 < 30) ? (bi + 64) : bi0;        // fetch for t2+2 (tail: harmless reload)
        ulonglong2 n0v = Bp[bn];
        ulonglong2 n1v = Bp[bn + 32];

        #pragma unroll
        for (int r = 0; r < ROWS; r++) {
            ulonglong2 A01 = Ap[r * (JK / 2) + abase + t2];  // {a_k,a_k},{a_k1,a_k1}
            FMA2(acc[r][0], A01.x, c0.x, acc[r][0]);
            FMA2(acc[r][1], A01.x, c0.y, acc[r][1]);
            FMA2(acc[r][0], A01.y, c1.x, acc[r][0]);
            FMA2(acc[r][1], A01.y, c1.y, acc[r][1]);
        }
        c0 = d0; c1 = d1;
        d0 = n0v; d1 = n1v;
    }

    // ---- Fold the two k-halves within the warp (lanes L <-> L+16) ----
    #pragma unroll
    for (int r = 0; r < ROWS; r++)
        #pragma unroll
        for (int p = 0; p < 2; p++) {
            u64 other = __shfl_xor_sync(0xffffffffu, acc[r][p], 16);
            ADD2(acc[r][p], acc[r][p], other);
        }

    // ---- Cross-warp reduction in SMEM (aliases a2_s after sync) ----
    __syncthreads();                 // everyone done reading a2_s
    u64* red = a2_s;                 // red[(kq*ROWS + r)*32 + pair]  (16 KB)
    if (khalf == 0) {
        #pragma unroll
        for (int r = 0; r < ROWS; r++)
            #pragma unroll
            for (int p = 0; p < 2; p++)
                red[(kq * ROWS + r) * 32 + pg * 2 + p] = acc[r][p];
    }
    __syncthreads();

    // ---- Epilogue: 256 threads x 1 output-pair (8 rows x 32 pairs) ----
    {
        int r  = tid >> 5;           // 0..7
        int pr = tid & 31;           // o-pair 0..31 within the half
        u64 s = red[(0 * ROWS + r) * 32 + pr];
        #pragma unroll
        for (int w = 1; w < 8; w++)
            ADD2(s, s, red[(w * ROWS + r) * 32 + pr]);
        float2 bv = ((const float2*)bias)[ohalf * 32 + pr];
        u64 bp;
        asm("mov.b64 %0, {%1, %2};" : "=l"(bp) : "r"(__float_as_uint(bv.x)), "r"(__float_as_uint(bv.y)));
        ADD2(s, s, bp);
        unsigned lo = (unsigned)(s & 0xFFFFFFFFull);
        unsigned hi = (unsigned)(s >> 32);
        ((float2*)out)[(n0 + r) * (D_OUT / 2) + ohalf * 32 + pr] =
            make_float2(__uint_as_float(lo), __uint_as_float(hi));
    }
}

extern "C" void kernel_launch(void* const* d_in, const int* in_sizes, int n_in,
                              void* d_out, int out_size) {
    const float* x       = (const float*)d_in[0];   // [1024,128]
    const float* coeffs  = (const float*)d_in[1];   // [128,128,8]
    const float* weights = (const float*)d_in[2];   // [128,128]
    const float* bias    = (const float*)d_in[3];   // [128]
    float* out = (float*)d_out;                     // [1024,128]

    cudaFuncSetAttribute(kan_main_kernel,
                         cudaFuncAttributeMaxDynamicSharedMemorySize, SMEM_BYTES);

    build_wc_kernel<<<(JK * D_OUT) / 256, 256>>>(coeffs, weights);
    dim3 grid(N_ROWS / ROWS, 2);                    // (128, 2)
    kan_main_kernel<<<grid, 256, SMEM_BYTES>>>(x, bias, out);
}

// round 10
// speedup vs baseline: 1.6598x; 1.6598x over previous
#include <cuda_runtime.h>
#include <cstdint>

// KAN layer as GEMM: out[1024,128] = A[1024,1024] @ B[1024,128] + bias
//   A[n, j*8+k] = Catmull-Rom basis weight (scalar fp32, built per n-tile in padded SMEM)
//   B[k, o]     = weights[o,j]*coeffs[o,j,k&7]  (row-major [k][o], built once, 512 KB)
//
// Main kernel: grid 128 (n-tiles of 8 rows), 256 threads, ONE block per SM (single wave).
//   warp = K-eighth (128 k); khalf = lane>>4 -> 64-k sub-slice; pg = lane&15.
//   Lane owns o-pairs {pg, pg+16, pg+32, pg+48} (strided: B LDG.64 contiguous across lanes).
//   Thread tile: 8 rows x 4 o-pairs x 64 k; A via scalar LDS.128 + mov.b64 dup (ALU pipe).
//   Reduce: shfl_xor(16) khalf fold -> SMEM (aliased on A tile) across 8 warps.

#define D_IN  128
#define D_OUT 128
#define KNOTS 8
#define N_ROWS 1024
#define JK 1024
#define ROWS 8
#define ASTRIDE 1280   // padded row stride: saddr(k) = k + (k>>4)*4; max 1275

typedef unsigned long long u64;

__device__ float g_WC2[JK * D_OUT];   // [k][o] row-major

__global__ void build_wc_kernel(const float* __restrict__ coeffs,
                                const float* __restrict__ weights) {
    int f = blockIdx.x * blockDim.x + threadIdx.x;   // 0 .. 131071
    int o  = f & (D_OUT - 1);
    int k  = f >> 7;
    int j  = k >> 3;
    int kk = k & 7;
    g_WC2[f] = weights[o * D_IN + j] * coeffs[(o * D_IN + j) * KNOTS + kk];
}

#define FMA2(d, a, b, c) \
    asm("fma.rn.f32x2 %0, %1, %2, %3;" : "=l"(d) : "l"(a), "l"(b), "l"(c))
#define ADD2(d, a, b) \
    asm("add.rn.f32x2 %0, %1, %2;" : "=l"(d) : "l"(a), "l"(b))
#define DUP2(d, s) \
    asm("mov.b64 %0, {%1, %1};" : "=l"(d) : "r"(__float_as_uint(s)))

// Load 16 B values (4 k x 4 pairs) for k-base kn.
#define LOADB(buf, kn) do {                                         \
    const u64* _p = Bu + (size_t)(kn) * 64 + pg;                    \
    _Pragma("unroll")                                               \
    for (int _kk = 0; _kk < 4; _kk++)                               \
        _Pragma("unroll")                                           \
        for (int _pp = 0; _pp < 4; _pp++)                           \
            (buf)[_kk * 4 + _pp] = _p[_kk * 64 + _pp * 16];         \
} while (0)

// One 4-k compute step with B buffer `buf` at k-base kc.
#define STEP(buf, kc) do {                                          \
    int _sa = (kc) + (((kc) >> 4) << 2);                            \
    _Pragma("unroll")                                               \
    for (int _r = 0; _r < ROWS; _r++) {                             \
        float4 _av = *(const float4*)&a_s[_r * ASTRIDE + _sa];      \
        u64 _a0, _a1, _a2, _a3;                                     \
        DUP2(_a0, _av.x); DUP2(_a1, _av.y);                         \
        DUP2(_a2, _av.z); DUP2(_a3, _av.w);                         \
        _Pragma("unroll")                                           \
        for (int _pp = 0; _pp < 4; _pp++) {                         \
            FMA2(acc[_r][_pp], _a0, (buf)[_pp],      acc[_r][_pp]); \
            FMA2(acc[_r][_pp], _a1, (buf)[4 + _pp],  acc[_r][_pp]); \
            FMA2(acc[_r][_pp], _a2, (buf)[8 + _pp],  acc[_r][_pp]); \
            FMA2(acc[_r][_pp], _a3, (buf)[12 + _pp], acc[_r][_pp]); \
        }                                                           \
    }                                                               \
} while (0)

__global__ __launch_bounds__(256, 1) void kan_main_kernel(
    const float* __restrict__ x,
    const float* __restrict__ bias,
    float* __restrict__ out) {
    // A tile, scalar fp32, padded rows (saddr = k + (k>>4)*4) to avoid the
    // khalf 2-group bank conflict on the broadcast LDS.128.
    // 40 KB; reused as the u64 cross-warp reduction buffer after the mainloop.
    __shared__ alignas(16) float a_s[ROWS * ASTRIDE];

    const int tid   = threadIdx.x;
    const int lane  = tid & 31;
    const int kq    = tid >> 5;          // warp = K-eighth
    const int pg    = lane & 15;         // owns o-pairs {pg, pg+16, pg+32, pg+48}
    const int khalf = lane >> 4;         // 64-k sub-slice of the warp's 128-k slice
    const int n0    = blockIdx.x * ROWS;

    // ---- Stage 1: build basis tile (8 rows x 128 j), 4 evals/thread ----
    #pragma unroll
    for (int e = tid; e < ROWS * D_IN; e += 256) {
        int nn = e >> 7;
        int j  = e & (D_IN - 1);
        float xv = x[(n0 + nn) * D_IN + j];
        float xc = fminf(fmaxf(xv, -1.0f), 1.0f);
        float t  = (xc + 1.0f) * 3.5f;               // h = 2/7
        int idx  = min((int)floorf(t), 6);
        float u  = t - (float)idx;
        float u2 = u * u, u3 = u2 * u;
        float b0 = 0.5f * (-u3 + 2.0f * u2 - u);
        float b1 = 0.5f * (3.0f * u3 - 5.0f * u2 + 2.0f);
        float b2 = 0.5f * (-3.0f * u3 + 4.0f * u2 + u);
        float b3 = 0.5f * (u3 - u2);
        int p0 = max(idx - 1, 0);
        int p3 = min(idx + 2, 7);
        float v[8];
        #pragma unroll
        for (int k = 0; k < 8; k++) {
            float s = 0.0f;
            s += (k == p0)      ? b0 : 0.0f;
            s += (k == idx)     ? b1 : 0.0f;
            s += (k == idx + 1) ? b2 : 0.0f;
            s += (k == p3)      ? b3 : 0.0f;
            v[k] = s;
        }
        int k0 = j * 8;
        int sa = k0 + ((k0 >> 4) << 2);              // padded address (8 floats stay in-chunk)
        float4* dst = (float4*)&a_s[nn * ASTRIDE + sa];
        dst[0] = make_float4(v[0], v[1], v[2], v[3]);
        dst[1] = make_float4(v[4], v[5], v[6], v[7]);
    }
    __syncthreads();

    // ---- Stage 2: mainloop, 16 steps of 4 k, double-buffered B ----
    const int kb = kq * 128 + khalf * 64;            // this lane's first k
    const u64* __restrict__ Bu = (const u64*)g_WC2;  // 64 o-pairs per k-row

    u64 acc[ROWS][4];
    #pragma unroll
    for (int r = 0; r < ROWS; r++)
        #pragma unroll
        for (int p = 0; p < 4; p++) acc[r][p] = 0ull;

    u64 bufA[16], bufB[16];
    LOADB(bufA, kb);

    #pragma unroll 1
    for (int it = 0; it < 16; it += 2) {
        int kn1 = (it + 1 < 16) ? kb + 4 * (it + 1) : kb;   // tail: harmless reload
        LOADB(bufB, kn1);
        STEP(bufA, kb + 4 * it);
        int kn2 = (it + 2 < 16) ? kb + 4 * (it + 2) : kb;
        LOADB(bufA, kn2);
        STEP(bufB, kb + 4 * (it + 1));
    }

    // ---- Fold the two k-halves within the warp (lanes L <-> L+16) ----
    #pragma unroll
    for (int r = 0; r < ROWS; r++)
        #pragma unroll
        for (int p = 0; p < 4; p++) {
            u64 other = __shfl_xor_sync(0xffffffffu, acc[r][p], 16);
            ADD2(acc[r][p], acc[r][p], other);
        }

    // ---- Cross-warp reduction in SMEM (aliases a_s after sync) ----
    __syncthreads();                 // everyone done reading a_s
    u64* red = (u64*)a_s;            // red[(kq*8 + r)*64 + pair]  (32 KB of the 40)
    if (khalf == 0) {
        #pragma unroll
        for (int r = 0; r < ROWS; r++)
            #pragma unroll
            for (int p = 0; p < 4; p++)
                red[(kq * ROWS + r) * 64 + pg + 16 * p] = acc[r][p];
    }
    __syncthreads();

    // ---- Epilogue: 512 outputs (8 rows x 64 pairs), 2 per thread ----
    #pragma unroll
    for (int t = tid; t < ROWS * 64; t += 256) {
        int r  = t >> 6;             // 0..7
        int pr = t & 63;             // o-pair 0..63
        u64 s = red[(0 * ROWS + r) * 64 + pr];
        #pragma unroll
        for (int w = 1; w < 8; w++)
            ADD2(s, s, red[(w * ROWS + r) * 64 + pr]);
        float2 bv = ((const float2*)bias)[pr];
        u64 bp;
        asm("mov.b64 %0, {%1, %2};" : "=l"(bp)
            : "r"(__float_as_uint(bv.x)), "r"(__float_as_uint(bv.y)));
        ADD2(s, s, bp);
        unsigned lo = (unsigned)(s & 0xFFFFFFFFull);
        unsigned hi = (unsigned)(s >> 32);
        ((float2*)out)[(n0 + r) * (D_OUT / 2) + pr] =
            make_float2(__uint_as_float(lo), __uint_as_float(hi));
    }
}

extern "C" void kernel_launch(void* const* d_in, const int* in_sizes, int n_in,
                              void* d_out, int out_size) {
    const float* x       = (const float*)d_in[0];   // [1024,128]
    const float* coeffs  = (const float*)d_in[1];   // [128,128,8]
    const float* weights = (const float*)d_in[2];   // [128,128]
    const float* bias    = (const float*)d_in[3];   // [128]
    float* out = (float*)d_out;                     // [1024,128]

    build_wc_kernel<<<(JK * D_OUT) / 256, 256>>>(coeffs, weights);
    kan_main_kernel<<<N_ROWS / ROWS, 256>>>(x, bias, out);
}

// round 12
// speedup vs baseline: 2.2312x; 1.3442x over previous
#include <cuda_runtime.h>
#include <cuda_bf16.h>
#include <cstdint>

// KAN layer as tensor-core GEMM (generic mma.sync path; tcgen05 blocked by
// harness compiling PTX at .target sm_103 without the 'a' suffix).
//   out[1024,128] = A[1024,1024] @ B^T + bias
//   A[n, j*8+k] = Catmull-Rom basis (built per tile, bf16 hi/lo split)
//   B[o, j*8+k] = weights[o,j]*coeffs[o,j,k] (precomputed bf16 hi/lo)
// 3-pass bf16 mma (hh + hl + lh), fp32 accumulators ~ fp32 accuracy.
//
// Main kernel: grid (16 m-tiles x 8 k-chunks) = 128 blocks, 256 threads.
//   8 warps = 4 m16-slices x 2 n64-halves. Warp tile: m16 x n64 x k128.
//   ldmatrix from padded row-major SMEM (272B row stride: conflict-free).
//   Partials -> g_part[kc][m][o]; reduce kernel sums + bias (deterministic).

#define D_IN  128
#define D_OUT 128
#define KNOTS 8
#define N_ROWS 1024
#define JK 1024
#define NKC 8
#define KCHUNK 128
#define MT 64                 // m rows per block

#define RSB 272               // SMEM row stride in bytes (136 bf16)
#define SM_AHI 0
#define SM_ALO (SM_AHI + MT * RSB)        // 17408
#define SM_BHI (SM_ALO + MT * RSB)        // 34816
#define SM_BLO (SM_BHI + D_OUT * RSB)     // 69632
#define SM_TOTAL (SM_BLO + D_OUT * RSB)   // 104448

__device__ __nv_bfloat16 g_Bhi[D_OUT * JK];     // [o][k]
__device__ __nv_bfloat16 g_Blo[D_OUT * JK];
__device__ float g_part[NKC * N_ROWS * D_OUT];  // 4 MB scratch

__device__ __forceinline__ uint32_t smem_u32(const void* p) {
    uint32_t a;
    asm("{ .reg .u64 t; cvta.to.shared.u64 t, %1; cvt.u32.u64 %0, t; }" : "=r"(a) : "l"(p));
    return a;
}

#define LDSM4(r0, r1, r2, r3, addr) \
    asm volatile("ldmatrix.sync.aligned.m8n8.x4.shared.b16 {%0,%1,%2,%3}, [%4];" \
        : "=r"(r0), "=r"(r1), "=r"(r2), "=r"(r3) : "r"(addr))

#define MMA16816(c, a0, a1, a2, a3, b0, b1) \
    asm volatile("mma.sync.aligned.m16n8k16.row.col.f32.bf16.bf16.f32 " \
        "{%0,%1,%2,%3}, {%4,%5,%6,%7}, {%8,%9}, {%0,%1,%2,%3};" \
        : "+f"((c)[0]), "+f"((c)[1]), "+f"((c)[2]), "+f"((c)[3]) \
        : "r"(a0), "r"(a1), "r"(a2), "r"(a3), "r"(b0), "r"(b1))

// ---------- preprocessing: B = w*coeff, split into bf16 hi/lo ----------
__global__ void build_b_kernel(const float* __restrict__ coeffs,
                               const float* __restrict__ weights) {
    int f = blockIdx.x * blockDim.x + threadIdx.x;   // 0 .. 131071
    int k = f & (JK - 1);
    int o = f >> 10;
    int j = k >> 3, kk = k & 7;
    float b = weights[o * D_IN + j] * coeffs[(o * D_IN + j) * KNOTS + kk];
    __nv_bfloat16 hi = __float2bfloat16(b);
    g_Bhi[f] = hi;
    g_Blo[f] = __float2bfloat16(b - __bfloat162float(hi));
}

// ---------- main tile kernel ----------
__global__ __launch_bounds__(256, 1) void kan_mma_kernel(const float* __restrict__ x) {
    extern __shared__ __align__(16) char smem[];
    const uint32_t sb = smem_u32(smem);
    const int tid  = threadIdx.x;
    const int wid  = tid >> 5;
    const int lane = tid & 31;
    const int wm   = wid & 3;        // m16 slice
    const int wn   = wid >> 2;       // n64 half
    const int mt   = blockIdx.x;     // m-tile (64 rows)
    const int kc   = blockIdx.y;     // k-chunk (128 k)

    // ---- Stage 1a: build A tile (64 rows x 16 j = 128 k), bf16 hi/lo ----
    #pragma unroll
    for (int e = tid; e < MT * 16; e += 256) {
        int m  = e >> 4;
        int jl = e & 15;
        int j  = kc * 16 + jl;
        float xv = x[(mt * MT + m) * D_IN + j];
        float xc = fminf(fmaxf(xv, -1.0f), 1.0f);
        float t  = (xc + 1.0f) * 3.5f;               // h = 2/7
        int idx  = min((int)floorf(t), 6);
        float u  = t - (float)idx;
        float u2 = u * u, u3 = u2 * u;
        float c0 = 0.5f * (-u3 + 2.0f * u2 - u);
        float c1 = 0.5f * (3.0f * u3 - 5.0f * u2 + 2.0f);
        float c2 = 0.5f * (-3.0f * u3 + 4.0f * u2 + u);
        float c3 = 0.5f * (u3 - u2);
        int p0 = max(idx - 1, 0);
        int p3 = min(idx + 2, 7);
        float v[8];
        #pragma unroll
        for (int k = 0; k < 8; k++) {
            float s = 0.0f;
            s += (k == p0)      ? c0 : 0.0f;
            s += (k == idx)     ? c1 : 0.0f;
            s += (k == idx + 1) ? c2 : 0.0f;
            s += (k == p3)      ? c3 : 0.0f;
            v[k] = s;
        }
        __nv_bfloat162 hi[4], lo[4];
        #pragma unroll
        for (int p = 0; p < 4; p++) {
            __nv_bfloat16 h0 = __float2bfloat16(v[2 * p]);
            __nv_bfloat16 h1 = __float2bfloat16(v[2 * p + 1]);
            hi[p] = __nv_bfloat162(h0, h1);
            lo[p] = __nv_bfloat162(
                __float2bfloat16(v[2 * p]     - __bfloat162float(h0)),
                __float2bfloat16(v[2 * p + 1] - __bfloat162float(h1)));
        }
        int off = m * RSB + jl * 16;
        *(uint4*)(smem + SM_AHI + off) = *(uint4*)hi;
        *(uint4*)(smem + SM_ALO + off) = *(uint4*)lo;
    }

    // ---- Stage 1b: load B chunk (128 o x 128 k), bf16 hi/lo ----
    #pragma unroll
    for (int e = tid; e < D_OUT * 16; e += 256) {
        int o = e >> 4;
        int c = e & 15;                              // 16B chunk = 8 k
        int soff = o * RSB + c * 16;
        int goff = o * JK + kc * KCHUNK + c * 8;
        *(uint4*)(smem + SM_BHI + soff) = *(const uint4*)&g_Bhi[goff];
        *(uint4*)(smem + SM_BLO + soff) = *(const uint4*)&g_Blo[goff];
    }
    __syncthreads();

    // ---- Stage 2: mainloop, 8 k16 blocks x 4 n16 groups x 3 passes ----
    // A frag lane addr: row = wm*16 + (L&7) + ((L>>3)&1)*8, col16 = (L>>4)
    // B frag lane addr: row = n0 + (L&7) + (L>>4)*8,       col16 = (L>>3)&1
    const uint32_t a_lane = (uint32_t)((wm * 16 + (lane & 7) + ((lane >> 3) & 1) * 8) * RSB
                                       + (lane >> 4) * 16);
    const uint32_t b_lane = (uint32_t)(((lane & 7) + (lane >> 4) * 8) * RSB
                                       + ((lane >> 3) & 1) * 16);
    const uint32_t aHI = sb + SM_AHI + a_lane;
    const uint32_t aLO = sb + SM_ALO + a_lane;
    const uint32_t bHI = sb + SM_BHI + b_lane + (uint32_t)(wn * 64 * RSB);
    const uint32_t bLO = sb + SM_BLO + b_lane + (uint32_t)(wn * 64 * RSB);

    float acc[8][4];
    #pragma unroll
    for (int nb = 0; nb < 8; nb++)
        #pragma unroll
        for (int q = 0; q < 4; q++) acc[nb][q] = 0.0f;

    #pragma unroll 1
    for (int kb = 0; kb < 8; kb++) {
        uint32_t koff = (uint32_t)(kb * 32);         // 16 k * 2B
        uint32_t ah0, ah1, ah2, ah3, al0, al1, al2, al3;
        LDSM4(ah0, ah1, ah2, ah3, aHI + koff);
        LDSM4(al0, al1, al2, al3, aLO + koff);

        #pragma unroll
        for (int ng = 0; ng < 4; ng++) {             // n16 group
            uint32_t noff = (uint32_t)(ng * 16 * RSB) + koff;
            uint32_t bh0, bh1, bh2, bh3, bl0, bl1, bl2, bl3;
            LDSM4(bh0, bh1, bh2, bh3, bHI + noff);
            LDSM4(bl0, bl1, bl2, bl3, bLO + noff);

            // n-block 2*ng: b frags (bh0,bh1) / (bl0,bl1)
            MMA16816(acc[2 * ng],     ah0, ah1, ah2, ah3, bh0, bh1);
            MMA16816(acc[2 * ng],     ah0, ah1, ah2, ah3, bl0, bl1);
            MMA16816(acc[2 * ng],     al0, al1, al2, al3, bh0, bh1);
            // n-block 2*ng+1: (bh2,bh3) / (bl2,bl3)
            MMA16816(acc[2 * ng + 1], ah0, ah1, ah2, ah3, bh2, bh3);
            MMA16816(acc[2 * ng + 1], ah0, ah1, ah2, ah3, bl2, bl3);
            MMA16816(acc[2 * ng + 1], al0, al1, al2, al3, bh2, bh3);
        }
    }

    // ---- Stage 3: write partials. c frag: thread t -> rows gid, gid+8; cols tig*2,+1 ----
    {
        const int gid = lane >> 2;
        const int tig = lane & 3;
        const int row0 = mt * MT + wm * 16 + gid;
        float* base = &g_part[(size_t)kc * (N_ROWS * D_OUT)];
        #pragma unroll
        for (int nb = 0; nb < 8; nb++) {
            int col = wn * 64 + nb * 8 + tig * 2;
            *(float2*)&base[(size_t)row0 * D_OUT + col]       = make_float2(acc[nb][0], acc[nb][1]);
            *(float2*)&base[(size_t)(row0 + 8) * D_OUT + col] = make_float2(acc[nb][2], acc[nb][3]);
        }
    }
}

// ---------- reduce: sum 8 k-chunk partials + bias ----------
__global__ void reduce_kernel(const float* __restrict__ bias, float* __restrict__ out) {
    int t = blockIdx.x * blockDim.x + threadIdx.x;   // 0 .. 32767 (float4 tasks)
    int m  = t >> 5;
    int c4 = (t & 31) * 4;
    float4 s = *(const float4*)&g_part[(size_t)m * D_OUT + c4];
    #pragma unroll
    for (int kcq = 1; kcq < NKC; kcq++) {
        float4 p = *(const float4*)&g_part[((size_t)kcq * N_ROWS + m) * D_OUT + c4];
        s.x += p.x; s.y += p.y; s.z += p.z; s.w += p.w;
    }
    float4 bv = *(const float4*)&bias[c4];
    s.x += bv.x; s.y += bv.y; s.z += bv.z; s.w += bv.w;
    *(float4*)&out[(size_t)m * D_OUT + c4] = s;
}

extern "C" void kernel_launch(void* const* d_in, const int* in_sizes, int n_in,
                              void* d_out, int out_size) {
    const float* x       = (const float*)d_in[0];   // [1024,128]
    const float* coeffs  = (const float*)d_in[1];   // [128,128,8]
    const float* weights = (const float*)d_in[2];   // [128,128]
    const float* bias    = (const float*)d_in[3];   // [128]
    float* out = (float*)d_out;                     // [1024,128]

    cudaFuncSetAttribute(kan_mma_kernel,
                         cudaFuncAttributeMaxDynamicSharedMemorySize, SM_TOTAL);

    build_b_kernel<<<(D_OUT * JK) / 256, 256>>>(coeffs, weights);
    dim3 grid(N_ROWS / MT, NKC);                    // (16, 8)
    kan_mma_kernel<<<grid, 256, SM_TOTAL>>>(x);
    reduce_kernel<<<(N_ROWS * D_OUT / 4) / 256, 256>>>(bias, out);
}

// round 13
// speedup vs baseline: 2.5889x; 1.1603x over previous
#include <cuda_runtime.h>
#include <cuda_bf16.h>
#include <cstdint>

// KAN layer as tensor-core GEMM (generic mma.sync path; tcgen05 blocked by
// harness compiling PTX at .target sm_103 without the 'a' suffix).
//   out[1024,128] = A[1024,1024] @ B^T + bias
//   A[n, j*8+k] = Catmull-Rom basis (built per tile, bf16 hi/lo split)
//   B[o, j*8+k] = weights[o,j]*coeffs[o,j,k]  (built IN-KERNEL per chunk, bf16 hi/lo)
// 3-pass bf16 mma (hh + hl + lh), fp32 accumulators ~ fp32 accuracy.
//
// Main kernel: grid (16 m-tiles x 8 k-chunks) = 128 blocks, 256 threads.
//   8 warps = 4 m16-slices x 2 n64-halves. Warp tile: m16 x n64 x k128.
//   ldmatrix from padded row-major SMEM (272B row stride: conflict-free).
//   Partials -> g_part[kc][m][o]; reduce kernel sums + bias (deterministic).

#define D_IN  128
#define D_OUT 128
#define KNOTS 8
#define N_ROWS 1024
#define JK 1024
#define NKC 8
#define KCHUNK 128
#define MT 64                 // m rows per block

#define RSB 272               // SMEM row stride in bytes (136 bf16)
#define SM_AHI 0
#define SM_ALO (SM_AHI + MT * RSB)        // 17408
#define SM_BHI (SM_ALO + MT * RSB)        // 34816
#define SM_BLO (SM_BHI + D_OUT * RSB)     // 69632
#define SM_TOTAL (SM_BLO + D_OUT * RSB)   // 104448

__device__ float g_part[NKC * N_ROWS * D_OUT];  // 4 MB scratch

__device__ __forceinline__ uint32_t smem_u32(const void* p) {
    uint32_t a;
    asm("{ .reg .u64 t; cvta.to.shared.u64 t, %1; cvt.u32.u64 %0, t; }" : "=r"(a) : "l"(p));
    return a;
}

#define LDSM4(r0, r1, r2, r3, addr) \
    asm volatile("ldmatrix.sync.aligned.m8n8.x4.shared.b16 {%0,%1,%2,%3}, [%4];" \
        : "=r"(r0), "=r"(r1), "=r"(r2), "=r"(r3) : "r"(addr))

#define MMA16816(c, a0, a1, a2, a3, b0, b1) \
    asm volatile("mma.sync.aligned.m16n8k16.row.col.f32.bf16.bf16.f32 " \
        "{%0,%1,%2,%3}, {%4,%5,%6,%7}, {%8,%9}, {%0,%1,%2,%3};" \
        : "+f"((c)[0]), "+f"((c)[1]), "+f"((c)[2]), "+f"((c)[3]) \
        : "r"(a0), "r"(a1), "r"(a2), "r"(a3), "r"(b0), "r"(b1))

// ---------- main tile kernel ----------
__global__ __launch_bounds__(256, 1) void kan_mma_kernel(
    const float* __restrict__ x,
    const float* __restrict__ coeffs,
    const float* __restrict__ weights) {
    extern __shared__ __align__(16) char smem[];
    const uint32_t sb = smem_u32(smem);
    const int tid  = threadIdx.x;
    const int wid  = tid >> 5;
    const int lane = tid & 31;
    const int wm   = wid & 3;        // m16 slice
    const int wn   = wid >> 2;       // n64 half
    const int mt   = blockIdx.x;     // m-tile (64 rows)
    const int kc   = blockIdx.y;     // k-chunk (128 k)

    // ---- Stage 1a: build A tile (64 rows x 16 j = 128 k), bf16 hi/lo ----
    #pragma unroll
    for (int e = tid; e < MT * 16; e += 256) {
        int m  = e >> 4;
        int jl = e & 15;
        int j  = kc * 16 + jl;
        float xv = x[(mt * MT + m) * D_IN + j];
        float xc = fminf(fmaxf(xv, -1.0f), 1.0f);
        float t  = (xc + 1.0f) * 3.5f;               // h = 2/7
        int idx  = min((int)floorf(t), 6);
        float u  = t - (float)idx;
        float u2 = u * u, u3 = u2 * u;
        float c0 = 0.5f * (-u3 + 2.0f * u2 - u);
        float c1 = 0.5f * (3.0f * u3 - 5.0f * u2 + 2.0f);
        float c2 = 0.5f * (-3.0f * u3 + 4.0f * u2 + u);
        float c3 = 0.5f * (u3 - u2);
        int p0 = max(idx - 1, 0);
        int p3 = min(idx + 2, 7);
        float v[8];
        #pragma unroll
        for (int k = 0; k < 8; k++) {
            float s = 0.0f;
            s += (k == p0)      ? c0 : 0.0f;
            s += (k == idx)     ? c1 : 0.0f;
            s += (k == idx + 1) ? c2 : 0.0f;
            s += (k == p3)      ? c3 : 0.0f;
            v[k] = s;
        }
        __nv_bfloat162 hi[4], lo[4];
        #pragma unroll
        for (int p = 0; p < 4; p++) {
            __nv_bfloat16 h0 = __float2bfloat16(v[2 * p]);
            __nv_bfloat16 h1 = __float2bfloat16(v[2 * p + 1]);
            hi[p] = __nv_bfloat162(h0, h1);
            lo[p] = __nv_bfloat162(
                __float2bfloat16(v[2 * p]     - __bfloat162float(h0)),
                __float2bfloat16(v[2 * p + 1] - __bfloat162float(h1)));
        }
        int off = m * RSB + jl * 16;
        *(uint4*)(smem + SM_AHI + off) = *(uint4*)hi;
        *(uint4*)(smem + SM_ALO + off) = *(uint4*)lo;
    }

    // ---- Stage 1b: BUILD B chunk in-kernel (128 o x 16 j = 128 k), hi/lo ----
    // b = weights[o,j] * coeffs[o,j,kk]; fully-coalesced float4 coeff loads.
    #pragma unroll
    for (int e = tid; e < D_OUT * 16; e += 256) {
        int o  = e >> 4;
        int jl = e & 15;
        int j  = kc * 16 + jl;
        int oj = o * D_IN + j;
        float w = weights[oj];
        float4 cA = *(const float4*)&coeffs[oj * KNOTS];
        float4 cB = *(const float4*)&coeffs[oj * KNOTS + 4];
        float v[8] = { w * cA.x, w * cA.y, w * cA.z, w * cA.w,
                       w * cB.x, w * cB.y, w * cB.z, w * cB.w };
        __nv_bfloat162 hi[4], lo[4];
        #pragma unroll
        for (int p = 0; p < 4; p++) {
            __nv_bfloat16 h0 = __float2bfloat16(v[2 * p]);
            __nv_bfloat16 h1 = __float2bfloat16(v[2 * p + 1]);
            hi[p] = __nv_bfloat162(h0, h1);
            lo[p] = __nv_bfloat162(
                __float2bfloat16(v[2 * p]     - __bfloat162float(h0)),
                __float2bfloat16(v[2 * p + 1] - __bfloat162float(h1)));
        }
        int soff = o * RSB + jl * 16;
        *(uint4*)(smem + SM_BHI + soff) = *(uint4*)hi;
        *(uint4*)(smem + SM_BLO + soff) = *(uint4*)lo;
    }
    __syncthreads();

    // ---- Stage 2: mainloop, 8 k16 blocks x 4 n16 groups x 3 passes ----
    // A frag lane addr: row = wm*16 + (L&7) + ((L>>3)&1)*8, col16 = (L>>4)
    // B frag lane addr: row = n0 + (L&7) + (L>>4)*8,       col16 = (L>>3)&1
    const uint32_t a_lane = (uint32_t)((wm * 16 + (lane & 7) + ((lane >> 3) & 1) * 8) * RSB
                                       + (lane >> 4) * 16);
    const uint32_t b_lane = (uint32_t)(((lane & 7) + (lane >> 4) * 8) * RSB
                                       + ((lane >> 3) & 1) * 16);
    const uint32_t aHI = sb + SM_AHI + a_lane;
    const uint32_t aLO = sb + SM_ALO + a_lane;
    const uint32_t bHI = sb + SM_BHI + b_lane + (uint32_t)(wn * 64 * RSB);
    const uint32_t bLO = sb + SM_BLO + b_lane + (uint32_t)(wn * 64 * RSB);

    float acc[8][4];
    #pragma unroll
    for (int nb = 0; nb < 8; nb++)
        #pragma unroll
        for (int q = 0; q < 4; q++) acc[nb][q] = 0.0f;

    #pragma unroll 1
    for (int kb = 0; kb < 8; kb++) {
        uint32_t koff = (uint32_t)(kb * 32);         // 16 k * 2B
        uint32_t ah0, ah1, ah2, ah3, al0, al1, al2, al3;
        LDSM4(ah0, ah1, ah2, ah3, aHI + koff);
        LDSM4(al0, al1, al2, al3, aLO + koff);

        #pragma unroll
        for (int ng = 0; ng < 4; ng++) {             // n16 group
            uint32_t noff = (uint32_t)(ng * 16 * RSB) + koff;
            uint32_t bh0, bh1, bh2, bh3, bl0, bl1, bl2, bl3;
            LDSM4(bh0, bh1, bh2, bh3, bHI + noff);
            LDSM4(bl0, bl1, bl2, bl3, bLO + noff);

            // n-block 2*ng: b frags (bh0,bh1) / (bl0,bl1)
            MMA16816(acc[2 * ng],     ah0, ah1, ah2, ah3, bh0, bh1);
            MMA16816(acc[2 * ng],     ah0, ah1, ah2, ah3, bl0, bl1);
            MMA16816(acc[2 * ng],     al0, al1, al2, al3, bh0, bh1);
            // n-block 2*ng+1: (bh2,bh3) / (bl2,bl3)
            MMA16816(acc[2 * ng + 1], ah0, ah1, ah2, ah3, bh2, bh3);
            MMA16816(acc[2 * ng + 1], ah0, ah1, ah2, ah3, bl2, bl3);
            MMA16816(acc[2 * ng + 1], al0, al1, al2, al3, bh2, bh3);
        }
    }

    // ---- Stage 3: write partials. c frag: thread t -> rows gid, gid+8; cols tig*2,+1 ----
    {
        const int gid = lane >> 2;
        const int tig = lane & 3;
        const int row0 = mt * MT + wm * 16 + gid;
        float* base = &g_part[(size_t)kc * (N_ROWS * D_OUT)];
        #pragma unroll
        for (int nb = 0; nb < 8; nb++) {
            int col = wn * 64 + nb * 8 + tig * 2;
            *(float2*)&base[(size_t)row0 * D_OUT + col]       = make_float2(acc[nb][0], acc[nb][1]);
            *(float2*)&base[(size_t)(row0 + 8) * D_OUT + col] = make_float2(acc[nb][2], acc[nb][3]);
        }
    }
}

// ---------- reduce: sum 8 k-chunk partials + bias ----------
__global__ void reduce_kernel(const float* __restrict__ bias, float* __restrict__ out) {
    int t = blockIdx.x * blockDim.x + threadIdx.x;   // 0 .. 32767 (float4 tasks)
    int m  = t >> 5;
    int c4 = (t & 31) * 4;
    float4 s = *(const float4*)&g_part[(size_t)m * D_OUT + c4];
    #pragma unroll
    for (int kcq = 1; kcq < NKC; kcq++) {
        float4 p = *(const float4*)&g_part[((size_t)kcq * N_ROWS + m) * D_OUT + c4];
        s.x += p.x; s.y += p.y; s.z += p.z; s.w += p.w;
    }
    float4 bv = *(const float4*)&bias[c4];
    s.x += bv.x; s.y += bv.y; s.z += bv.z; s.w += bv.w;
    *(float4*)&out[(size_t)m * D_OUT + c4] = s;
}

extern "C" void kernel_launch(void* const* d_in, const int* in_sizes, int n_in,
                              void* d_out, int out_size) {
    const float* x       = (const float*)d_in[0];   // [1024,128]
    const float* coeffs  = (const float*)d_in[1];   // [128,128,8]
    const float* weights = (const float*)d_in[2];   // [128,128]
    const float* bias    = (const float*)d_in[3];   // [128]
    float* out = (float*)d_out;                     // [1024,128]

    cudaFuncSetAttribute(kan_mma_kernel,
                         cudaFuncAttributeMaxDynamicSharedMemorySize, SM_TOTAL);

    dim3 grid(N_ROWS / MT, NKC);                    // (16, 8)
    kan_mma_kernel<<<grid, 256, SM_TOTAL>>>(x, coeffs, weights);
    reduce_kernel<<<(N_ROWS * D_OUT / 4) / 256, 256>>>(bias, out);
}